// round 7
// baseline (speedup 1.0000x reference)
#include <cuda_runtime.h>

// ---------------------------------------------------------------------------
// SparseCoupleDeConvTest: stride-2 sparse conv3d (CIN=32 -> COUT=64, K=3)
// followed by its exact adjoint (conv_transpose, transpose_kernel=True),
// masked to the sparse input coordinates, output channel-major.
//
// out[b, i, z, y, x] (only at sparse coords) =
//   sum_{(o,k): 2o+k=(z,y,x), o in bounds} mid[b, o, j] * w2[k, i, j]
// mid[b, o, j] = sum_{tap k', q sparse at 2o+k'} feat[q, i'] * w1[k', i', j]
// ---------------------------------------------------------------------------

typedef unsigned long long ull;

namespace {
constexpr int Dz = 41, Hy = 159, Wx = 159;
constexpr int OD = 20, OH = 79, OW = 79;
constexpr int CIN = 32, COUT = 64;
constexpr int B = 2;
constexpr int NVOX = B * Dz * Hy * Wx;          // 2,073,042
constexpr int NMID = B * OD * OH * OW;          // 249,640
}

// Scratch (allocation-free: __device__ globals)
__device__ int    g_idxmap[NVOX];                       // voxel -> point id or -1
__device__ float  g_mid[(size_t)NMID * COUT];           // dense mid activations (~64 MB)
__device__ float2 g_w2p[27 * (COUT / 2) * CIN];         // w2 repacked [k][jp][i] -> (w2[k,i,2jp], w2[k,i,2jp+1])

// ---- packed fp32x2 helpers (sm_103a) --------------------------------------
__device__ __forceinline__ ull ffma2(ull a, ull b, ull c) {
    ull d;
    asm("fma.rn.f32x2 %0, %1, %2, %3;" : "=l"(d) : "l"(a), "l"(b), "l"(c));
    return d;
}
__device__ __forceinline__ ull fadd2(ull a, ull b) {
    ull d;
    asm("add.rn.f32x2 %0, %1, %2;" : "=l"(d) : "l"(a), "l"(b));
    return d;
}
__device__ __forceinline__ ull pack2(float x, float y) {
    ull r;
    asm("mov.b64 %0, {%1, %2};" : "=l"(r) : "f"(x), "f"(y));
    return r;
}
__device__ __forceinline__ float2 unpack2(ull a) {
    float2 r;
    asm("mov.b64 {%0, %1}, %2;" : "=f"(r.x), "=f"(r.y) : "l"(a));
    return r;
}

// ---- setup kernels ---------------------------------------------------------

__global__ void zero_out_kernel(float4* __restrict__ out, int n4) {
    int i = blockIdx.x * blockDim.x + threadIdx.x;
    int stride = gridDim.x * blockDim.x;
    float4 z = make_float4(0.f, 0.f, 0.f, 0.f);
    for (; i < n4; i += stride) out[i] = z;
}

__global__ void fill_idx_kernel() {
    int i = blockIdx.x * blockDim.x + threadIdx.x;
    if (i < NVOX) g_idxmap[i] = -1;
}

__global__ void scatter_pts_kernel(const int* __restrict__ coors, int npts) {
    int n = blockIdx.x * blockDim.x + threadIdx.x;
    if (n >= npts) return;
    int4 c = ((const int4*)coors)[n];      // (b, z, y, x)
    g_idxmap[((c.x * Dz + c.y) * Hy + c.z) * Wx + c.w] = n;
}

// w2 layout (K,K,K,CIN,COUT): flat = k*2048 + i*64 + j.
// Repack to per-(k, j-pair) rows of CIN consecutive float2 so the back kernel's
// warp load of weights is a single 256B contiguous access.
__global__ void build_w2p_kernel(const float* __restrict__ w2) {
    int t = blockIdx.x * blockDim.x + threadIdx.x;
    if (t >= 27 * 32 * 32) return;
    int ci = t & 31;
    int jp = (t >> 5) & 31;
    int k  = t >> 10;
    const float* base = w2 + k * (CIN * COUT) + ci * COUT + 2 * jp;
    g_w2p[(k * 32 + jp) * 32 + ci] = make_float2(base[0], base[1]);
}

// ---- stage 1: sparse gather conv -> dense mid ------------------------------
// One warp per mid voxel. Lane l owns output channels (2l, 2l+1) as one f32x2
// accumulator. For each occupied tap: broadcast the 32 input features via shfl
// and FMA against w1[t][i1][2l:2l+2] (contiguous 8B per lane -> 256B/warp).
__global__ void __launch_bounds__(256) mid_kernel(
    const float* __restrict__ features, const float* __restrict__ w1)
{
    int gw = (blockIdx.x * 256 + threadIdx.x) >> 5;
    int lane = threadIdx.x & 31;
    if (gw >= NMID) return;

    int tmp = gw;
    int ox = tmp % OW; tmp /= OW;
    int oy = tmp % OH; tmp /= OH;
    int oz = tmp % OD;
    int b  = tmp / OD;

    int q = -1;
    if (lane < 27) {
        int tz = lane / 9;
        int tr = lane - tz * 9;
        int ty = tr / 3;
        int tx = tr - ty * 3;
        // VALID conv: 2*o + t always in bounds, no checks needed
        q = g_idxmap[((b * Dz + (2 * oz + tz)) * Hy + (2 * oy + ty)) * Wx + (2 * ox + tx)];
    }
    unsigned occ = __ballot_sync(0xffffffffu, q >= 0);

    ull acc0 = 0ull, acc1 = 0ull;
    const ull* w1u = (const ull*)w1;   // ull index: t*1024 + i1*32 + lane

    while (occ) {
        int t = __ffs(occ) - 1;
        occ &= occ - 1;
        int qq = __shfl_sync(0xffffffffu, q, t);
        float f = features[qq * CIN + lane];           // coalesced 128B
        const ull* wr = w1u + t * 1024 + lane;
#pragma unroll
        for (int i1 = 0; i1 < 32; i1 += 2) {
            float f0 = __shfl_sync(0xffffffffu, f, i1);
            float f1 = __shfl_sync(0xffffffffu, f, i1 + 1);
            acc0 = ffma2(pack2(f0, f0), __ldg(wr + (size_t)i1 * 32), acc0);
            acc1 = ffma2(pack2(f1, f1), __ldg(wr + (size_t)(i1 + 1) * 32), acc1);
        }
    }
    // Unconditional store: empty voxels write zeros (no pre-zero of g_mid needed)
    ((ull*)g_mid)[(size_t)gw * 32 + lane] = fadd2(acc0, acc1);
}

// ---- stage 2: adjoint gather at sparse points ------------------------------
// Candidate mid coords per dim: 2o + k = v, k in {0,1,2}, 0 <= o < O.
__device__ __forceinline__ int cands(int v, int O, int* os, int* ks) {
    if (v & 1) { os[0] = v >> 1; ks[0] = 1; return 1; }
    int n = 0, h = v >> 1;
    if (h < O) { os[n] = h;     ks[n] = 0; n++; }
    if (h > 0) { os[n] = h - 1; ks[n] = 2; n++; }
    return n;
}

// One warp per sparse point. Lane l owns input channel i = l.
// For each valid mid offset: warp stages the 64-wide mid row in shared memory,
// then 32 packed FMAs against the repacked w2 rows (contiguous per warp).
__global__ void __launch_bounds__(256) back_kernel(
    const int* __restrict__ coors, int npts, float* __restrict__ out)
{
    __shared__ ull smid[8][32];
    int w    = threadIdx.x >> 5;
    int lane = threadIdx.x & 31;
    int n = blockIdx.x * 8 + w;
    if (n >= npts) return;

    int4 c = ((const int4*)coors)[n];
    int b = c.x, z = c.y, y = c.z, x = c.w;

    int oz[2], kz[2], oy[2], ky[2], ox[2], kx[2];
    int na = cands(z, OD, oz, kz);
    int nb = cands(y, OH, oy, ky);
    int nc = cands(x, OW, ox, kx);

    ull acc0 = 0ull, acc1 = 0ull;
    const ull* w2u = (const ull*)g_w2p;   // ull index: k*1024 + jp*32 + lane
    const ull* midu = (const ull*)g_mid;

    for (int a = 0; a < na; a++)
        for (int bb = 0; bb < nb; bb++)
            for (int cc = 0; cc < nc; cc++) {
                int mo = ((b * OD + oz[a]) * OH + oy[bb]) * OW + ox[cc];
                int k  = (kz[a] * 3 + ky[bb]) * 3 + kx[cc];
                ull mv = midu[(size_t)mo * 32 + lane];   // coalesced 256B
                __syncwarp();
                smid[w][lane] = mv;
                __syncwarp();
                const ull* wr = w2u + k * 1024 + lane;
#pragma unroll
                for (int jp = 0; jp < 32; jp += 2) {
                    acc0 = ffma2(smid[w][jp],     __ldg(wr + (size_t)jp * 32),       acc0);
                    acc1 = ffma2(smid[w][jp + 1], __ldg(wr + (size_t)(jp + 1) * 32), acc1);
                }
            }

    float2 r = unpack2(fadd2(acc0, acc1));
    float v = r.x + r.y;
    // output layout (B, CIN, D, H, W)
    size_t oidx = (((size_t)(b * CIN + lane)) * Dz + z) * ((size_t)Hy * Wx)
                + (size_t)y * Wx + x;
    out[oidx] = v;
}

// ---------------------------------------------------------------------------

extern "C" void kernel_launch(void* const* d_in, const int* in_sizes, int n_in,
                              void* d_out, int out_size) {
    if (n_in < 4) return;
    const float* features = (const float*)d_in[0];
    const int*   coors    = (const int*)d_in[1];
    const float* w1       = (const float*)d_in[n_in - 2];
    const float* w2       = (const float*)d_in[n_in - 1];
    float* out = (float*)d_out;
    int npts = in_sizes[1] / 4;

    // 1) zero output (only sparse points get written later)
    int n4 = out_size / 4;   // out_size = 66,337,344 -> divisible by 4
    zero_out_kernel<<<2048, 256>>>((float4*)out, n4);

    // 2) rebuild voxel -> point index map
    fill_idx_kernel<<<(NVOX + 255) / 256, 256>>>();
    scatter_pts_kernel<<<(npts + 255) / 256, 256>>>(coors, npts);

    // 3) repack w2 for coalesced adjoint reads
    build_w2p_kernel<<<(27 * 32 * 32 + 255) / 256, 256>>>(w2);

    // 4) sparse gather conv -> dense mid
    mid_kernel<<<(NMID + 7) / 8, 256>>>(features, w1);

    // 5) adjoint gather + mask + channel-major scatter
    back_kernel<<<(npts + 7) / 8, 256>>>(coors, npts, out);
}